// round 12
// baseline (speedup 1.0000x reference)
#include <cuda_runtime.h>
#include <cstdint>

#define HH 8
#define DD 1024
#define SS 1024
#define MIDD 2048
#define SOUT 512

typedef long long ll;

// ---------------- scratch (device globals; no allocation allowed) ----------
// all packed arrays use the fragment-ready pair layout:
// per row, k16-block of 16 words: [hi(p) lo(p) hi(p+4) lo(p+4)] for p=0..3,
// where pair p packs elements (2p, 2p+1) as bf16x2 hi-word + residual lo-word.
__device__ uint32_t p_qkv[3ll * DD * SS];              // (d, s) per q
__device__ uint32_t p_z[(ll)HH * DD * MIDD];           // (d, m) per h
__device__ uint32_t p_s[3ll * HH * SS * DD];           // slot0 sqT (s,d), slot1 skT, slot2 sv (d,s)
__device__ uint32_t p_bm[(ll)HH * SS * SS];            // bT (t, s) per h
__device__ uint32_t p_att[(ll)SS * HH * DD];           // attT (t, h*D+d)
__device__ uint32_t p_y[(ll)SS * MIDD];                // (s, m)
__device__ uint32_t p_h[(ll)DD * SS];                  // h2 packed (d, s)
__device__ uint32_t p_h1t[(ll)SS * DD];                // h1T packed (s, d)
__device__ uint32_t p_x1[(ll)DD * MIDD];
__device__ uint32_t p_x2[(ll)DD * SOUT];
__device__ float    g_m [(ll)DD * SS];                 // fp32 mha out
__device__ float    g_hf[(ll)DD * SS];                 // fp32 h1
// packed inputs / weights
__device__ uint32_t p_inpT[(ll)SS * DD];               // inp transposed (s, d)
__device__ uint32_t p_enck[(ll)DD * SS];
__device__ uint32_t p_encv[(ll)DD * SS];
__device__ uint32_t p_wqkv1[3ll * DD * DD];
__device__ uint32_t p_wqkv2[(ll)DD * DD];
__device__ uint32_t p_W1a[(ll)HH * 3 * MIDD * SS];
__device__ uint32_t p_W2a[(ll)HH * 3 * SS * MIDD];
__device__ uint32_t p_W1b[(ll)HH * 3 * MIDD * SS];
__device__ uint32_t p_W2b[(ll)HH * 3 * SS * MIDD];
__device__ uint32_t p_c1w1[(ll)MIDD * HH * DD];
__device__ uint32_t p_c2w1[(ll)MIDD * HH * DD];
__device__ uint32_t p_c1w2[(ll)DD * MIDD];
__device__ uint32_t p_c2w2[(ll)DD * MIDD];
__device__ uint32_t p_l1w1[(ll)MIDD * SS];
__device__ uint32_t p_l1w2[(ll)SOUT * MIDD];
__device__ uint32_t p_l2w1[(ll)MIDD * SOUT];
__device__ uint32_t p_l2w2[(ll)SOUT * MIDD];

// ---------------- PTX helpers (base sm_103 features only) -------------------
__device__ __forceinline__ uint32_t smem_u32(const void* p) {
    uint32_t a;
    asm("{ .reg .u64 t; cvta.to.shared.u64 t, %1; cvt.u32.u64 %0, t; }"
        : "=r"(a) : "l"(p));
    return a;
}
__device__ __forceinline__ void cpa16(uint32_t dst, const void* src) {
    asm volatile("cp.async.cg.shared.global [%0], [%1], 16;"
                 :: "r"(dst), "l"(src) : "memory");
}
__device__ __forceinline__ void cp_commit() {
    asm volatile("cp.async.commit_group;" ::: "memory");
}
template<int NG>
__device__ __forceinline__ void cp_wait() {
    asm volatile("cp.async.wait_group %0;" :: "n"(NG) : "memory");
}

// two-term bf16 split of an element pair -> mma-ready hi-pair / lo-pair words
template<bool RELU>
__device__ __forceinline__ void pack2(float2 v, uint32_t& hi, uint32_t& lo) {
    if (RELU) { v.x = fmaxf(v.x, 0.f); v.y = fmaxf(v.y, 0.f); }
    asm("cvt.rn.bf16x2.f32 %0, %1, %2;" : "=r"(hi) : "f"(v.y), "f"(v.x));
    const float hx = __uint_as_float(hi << 16);
    const float hy = __uint_as_float(hi & 0xffff0000u);
    asm("cvt.rn.bf16x2.f32 %0, %1, %2;" : "=r"(lo) : "f"(v.y - hy), "f"(v.x - hx));
}

// word offset within a row for element column c (even): k16-block layout
__device__ __forceinline__ int pair_off(int c) {
    return ((c >> 4) << 4) + (((c >> 1) & 3) << 2) + (((c >> 3) & 1) << 1);
}

__device__ __forceinline__ void mma16(float* d, const uint32_t* a, const uint32_t* b) {
    asm volatile(
        "mma.sync.aligned.m16n8k16.row.col.f32.bf16.bf16.f32 "
        "{%0,%1,%2,%3}, {%4,%5,%6,%7}, {%8,%9}, {%0,%1,%2,%3};"
        : "+f"(d[0]), "+f"(d[1]), "+f"(d[2]), "+f"(d[3])
        : "r"(a[0]), "r"(a[1]), "r"(a[2]), "r"(a[3]), "r"(b[0]), "r"(b[1]));
}

// ---------------- pack kernels ----------------------------------------------
// row-major pack: fp32 X[R][C] -> packed same shape, pair layout along C
template<bool RELU>
__global__ __launch_bounds__(256) void pack_k(
    const float* __restrict__ src, uint32_t* __restrict__ dst, int C, int n4)
{
    const int i = blockIdx.x * 256 + threadIdx.x;
    if (i >= n4) return;
    const ll idx = (ll)i * 4;
    const int c = (int)(idx % C);
    const ll rowbase = idx - c;
    const float4 v = *(const float4*)(src + idx);
    uint2 w0, w1;
    pack2<RELU>(make_float2(v.x, v.y), w0.x, w0.y);
    pack2<RELU>(make_float2(v.z, v.w), w1.x, w1.y);
    *(uint2*)(dst + rowbase + pair_off(c))     = w0;
    *(uint2*)(dst + rowbase + pair_off(c + 2)) = w1;
}

// transpose-pack: fp32 X[R][C] -> packed Y[C][R], pairs along R
__global__ __launch_bounds__(256) void pt_k(
    const float* __restrict__ X, uint32_t* __restrict__ Y, int R, int C)
{
    const int i = blockIdx.x * 256 + threadIdx.x;
    const int total = C * (R >> 1);
    if (i >= total) return;
    const int c = i % C;
    const int p = i / C;
    const float f0 = X[(ll)(2 * p) * C + c];
    const float f1 = X[(ll)(2 * p + 1) * C + c];
    uint2 w;
    pack2<false>(make_float2(f0, f1), w.x, w.y);
    *(uint2*)(Y + (ll)c * R + pair_off(2 * p)) = w;
}

// ---------------- packed bf16x3 mma.sync GEMM (row-major x row-major) -------
// D[m][n] = sum_k a[m][k] * b[n][k]; both operands in fragment-ready layout.
//   EP: 0 = fp32 out, 1 = fp32 tanh out, 2 = packed out, 3 = packed+relu out.
// M,N mult of 128; K mult of 32. 256 threads (8 warps, 2x4 warp grid).

#define STR     40
#define TILE_W  (128 * STR)
#define STAGE_B (TILE_W * 4)
#define SMEM_DYN (4 * STAGE_B)

template<int EP>
__global__ __launch_bounds__(256, 2) void gemm_p(
    const uint32_t* __restrict__ Ag, const uint32_t* __restrict__ Bg, void* Cg,
    int M, int N, int K, ll sA, ll sB, ll sC, int ldC)
{
    extern __shared__ __align__(16) uint32_t smem[];
    const uint32_t sb = smem_u32(smem);

    const uint32_t* A = Ag + (ll)blockIdx.z * sA;
    const uint32_t* B = Bg + (ll)blockIdx.z * sB;
    const int m0 = blockIdx.y * 128;
    const int n0 = blockIdx.x * 128;

    const int tid = threadIdx.x;
    const int wid = tid >> 5, lid = tid & 31;
    const int wm = wid >> 2, wn = wid & 3;
    const int g = lid >> 2, tg = lid & 3;

    float acc[4][4][4];
    #pragma unroll
    for (int mi = 0; mi < 4; mi++)
        #pragma unroll
        for (int ni = 0; ni < 4; ni++)
            #pragma unroll
            for (int r = 0; r < 4; r++) acc[mi][ni][r] = 0.f;

    auto issue = [&](int t) {
        const int st = t & 1;
        const uint32_t abase = sb + (uint32_t)(st * 2) * STAGE_B;
        const uint32_t bbase = abase + STAGE_B;
        const int k0 = t << 5;
        #pragma unroll
        for (int i = 0; i < 4; i++) {
            int idx = tid + i * 256;
            int r = idx >> 3, kq = (idx & 7) << 2;
            cpa16(abase + (uint32_t)(r * STR + kq) * 4,
                  A + (ll)(m0 + r) * K + k0 + kq);
        }
        #pragma unroll
        for (int i = 0; i < 4; i++) {
            int idx = tid + i * 256;
            int r = idx >> 3, kq = (idx & 7) << 2;
            cpa16(bbase + (uint32_t)(r * STR + kq) * 4,
                  B + (ll)(n0 + r) * K + k0 + kq);
        }
    };

    const int T = K >> 5;
    issue(0);
    cp_commit();

    for (int t = 0; t < T; t++) {
        if (t + 1 < T) { issue(t + 1); cp_commit(); cp_wait<1>(); }
        else           { cp_wait<0>(); }
        __syncthreads();

        const uint32_t* As = smem + (t & 1) * 2 * TILE_W;
        const uint32_t* Bs = As + TILE_W;

        #pragma unroll
        for (int ks = 0; ks < 2; ks++) {
            const int kb = ks * 16;
            uint32_t bh[4][2], bl[4][2];
            #pragma unroll
            for (int ni = 0; ni < 4; ni++) {
                const uint4 r = *(const uint4*)(Bs + (wn * 32 + ni * 8 + g) * STR + kb + 4 * tg);
                bh[ni][0] = r.x; bl[ni][0] = r.y;
                bh[ni][1] = r.z; bl[ni][1] = r.w;
            }
            #pragma unroll
            for (int mi = 0; mi < 4; mi++) {
                const uint32_t* pa = As + (wm * 64 + mi * 16 + g) * STR + kb + 4 * tg;
                const uint4 r0 = *(const uint4*)pa;
                const uint4 r1 = *(const uint4*)(pa + 8 * STR);
                uint32_t ah[4] = {r0.x, r1.x, r0.z, r1.z};
                uint32_t al[4] = {r0.y, r1.y, r0.w, r1.w};
                #pragma unroll
                for (int ni = 0; ni < 4; ni++) {
                    mma16(acc[mi][ni], ah, bh[ni]);
                    mma16(acc[mi][ni], ah, bl[ni]);
                    mma16(acc[mi][ni], al, bh[ni]);
                }
            }
        }
        __syncthreads();
    }

    // ---- epilogue ----
    #pragma unroll
    for (int mi = 0; mi < 4; mi++) {
        #pragma unroll
        for (int ni = 0; ni < 4; ni++) {
            const int r0 = m0 + wm * 64 + mi * 16 + g;
            const int c  = n0 + wn * 32 + ni * 8 + 2 * tg;
            float2 v0 = make_float2(acc[mi][ni][0], acc[mi][ni][1]);
            float2 v1 = make_float2(acc[mi][ni][2], acc[mi][ni][3]);
            if (EP <= 1) {
                float* C = (float*)Cg + (ll)blockIdx.z * sC;
                if (EP == 1) {
                    v0.x = tanhf(v0.x); v0.y = tanhf(v0.y);
                    v1.x = tanhf(v1.x); v1.y = tanhf(v1.y);
                }
                *(float2*)(C + (ll)r0 * ldC + c)       = v0;
                *(float2*)(C + (ll)(r0 + 8) * ldC + c) = v1;
            } else {
                uint32_t* C = (uint32_t*)Cg + (ll)blockIdx.z * sC;
                const int off = pair_off(c);
                uint2 w0, w1;
                pack2<EP == 3>(v0, w0.x, w0.y);
                pack2<EP == 3>(v1, w1.x, w1.y);
                *(uint2*)(C + (ll)r0 * ldC + off)       = w0;
                *(uint2*)(C + (ll)(r0 + 8) * ldC + off) = w1;
            }
        }
    }
}

// ---------------- fused residual-add + LayerNorm -----------------------------
// OM: 0 = fp32 out, 2 = packed+relu out
template<int OM>
__global__ __launch_bounds__(256) void add_ln_k(
    const float* __restrict__ x, const float* __restrict__ m,
    const float* __restrict__ g, const float* __restrict__ b,
    void* __restrict__ o)
{
    const int row = blockIdx.x;
    const ll off = (ll)row * SS;
    float2 v[2];
    float sum = 0.f, sq = 0.f;
    #pragma unroll
    for (int j = 0; j < 2; j++) {
        int i2 = threadIdx.x * 2 + j * 512;
        float2 xv = *(const float2*)(x + off + i2);
        float2 mv = *(const float2*)(m + off + i2);
        v[j] = make_float2(xv.x + mv.x, xv.y + mv.y);
        sum += v[j].x + v[j].y;
        sq  += v[j].x * v[j].x + v[j].y * v[j].y;
    }
    #pragma unroll
    for (int o2 = 16; o2; o2 >>= 1) {
        sum += __shfl_xor_sync(0xffffffffu, sum, o2);
        sq  += __shfl_xor_sync(0xffffffffu, sq,  o2);
    }
    __shared__ float rs[8], rq[8];
    const int w = threadIdx.x >> 5, l = threadIdx.x & 31;
    if (l == 0) { rs[w] = sum; rq[w] = sq; }
    __syncthreads();
    if (w == 0) {
        float s2 = (l < 8) ? rs[l] : 0.f;
        float q2 = (l < 8) ? rq[l] : 0.f;
        #pragma unroll
        for (int o2 = 4; o2; o2 >>= 1) {
            s2 += __shfl_xor_sync(0xffffffffu, s2, o2);
            q2 += __shfl_xor_sync(0xffffffffu, q2, o2);
        }
        if (l == 0) { rs[0] = s2; rq[0] = q2; }
    }
    __syncthreads();
    const float mu  = rs[0] * (1.f / SS);
    const float var = rq[0] * (1.f / SS) - mu * mu;
    const float inv = rsqrtf(var + 1e-6f);
    #pragma unroll
    for (int j = 0; j < 2; j++) {
        int i2 = threadIdx.x * 2 + j * 512;
        float2 gv = *(const float2*)(g + i2);
        float2 bv = *(const float2*)(b + i2);
        float2 t = make_float2((v[j].x - mu) * inv * gv.x + bv.x,
                               (v[j].y - mu) * inv * gv.y + bv.y);
        if (OM == 0) {
            *(float2*)((float*)o + off + i2) = t;
        } else {
            uint2 wo;
            pack2<true>(t, wo.x, wo.y);
            *(uint2*)((uint32_t*)o + off + pair_off(i2)) = wo;
        }
    }
}

// ---------------- host orchestration ----------------------------------------
extern "C" void kernel_launch(void* const* d_in, const int* in_sizes, int n_in,
                              void* d_out, int out_size)
{
    const float* inp    = (const float*)d_in[0];
    const float* enc_k  = (const float*)d_in[1];
    const float* enc_v  = (const float*)d_in[2];
    const float* w_qkv1 = (const float*)d_in[3];
    const float* w_qkv2 = (const float*)d_in[4];
    const float* mh1_W1 = (const float*)d_in[5];
    const float* mh1_W2 = (const float*)d_in[6];
    const float* mh2_W1 = (const float*)d_in[7];
    const float* mh2_W2 = (const float*)d_in[8];
    const float* c1_w1  = (const float*)d_in[9];
    const float* c1_w2  = (const float*)d_in[10];
    const float* c2_w1  = (const float*)d_in[11];
    const float* c2_w2  = (const float*)d_in[12];
    const float* l1_w1  = (const float*)d_in[13];
    const float* l1_w2  = (const float*)d_in[14];
    const float* l2_w1  = (const float*)d_in[15];
    const float* l2_w2  = (const float*)d_in[16];
    const float* gamma  = (const float*)d_in[17];
    const float* beta   = (const float*)d_in[18];
    float* out = (float*)d_out;

    uint32_t *qkv, *z, *s, *bm, *att, *y, *hb, *h1t, *x1, *x2;
    uint32_t *pinpT, *penck, *pencv, *pw1, *pw2;
    uint32_t *W1a, *W2a, *W1b, *W2b, *c1a, *c2a, *c1b, *c2b;
    uint32_t *lw11, *lw12, *lw21, *lw22;
    float *mb, *hf;
    cudaGetSymbolAddress((void**)&qkv,  p_qkv);
    cudaGetSymbolAddress((void**)&z,    p_z);
    cudaGetSymbolAddress((void**)&s,    p_s);
    cudaGetSymbolAddress((void**)&bm,   p_bm);
    cudaGetSymbolAddress((void**)&att,  p_att);
    cudaGetSymbolAddress((void**)&y,    p_y);
    cudaGetSymbolAddress((void**)&hb,   p_h);
    cudaGetSymbolAddress((void**)&h1t,  p_h1t);
    cudaGetSymbolAddress((void**)&x1,   p_x1);
    cudaGetSymbolAddress((void**)&x2,   p_x2);
    cudaGetSymbolAddress((void**)&mb,   g_m);
    cudaGetSymbolAddress((void**)&hf,   g_hf);
    cudaGetSymbolAddress((void**)&pinpT, p_inpT);
    cudaGetSymbolAddress((void**)&penck, p_enck);
    cudaGetSymbolAddress((void**)&pencv, p_encv);
    cudaGetSymbolAddress((void**)&pw1,   p_wqkv1);
    cudaGetSymbolAddress((void**)&pw2,   p_wqkv2);
    cudaGetSymbolAddress((void**)&W1a,   p_W1a);
    cudaGetSymbolAddress((void**)&W2a,   p_W2a);
    cudaGetSymbolAddress((void**)&W1b,   p_W1b);
    cudaGetSymbolAddress((void**)&W2b,   p_W2b);
    cudaGetSymbolAddress((void**)&c1a,   p_c1w1);
    cudaGetSymbolAddress((void**)&c2a,   p_c2w1);
    cudaGetSymbolAddress((void**)&c1b,   p_c1w2);
    cudaGetSymbolAddress((void**)&c2b,   p_c2w2);
    cudaGetSymbolAddress((void**)&lw11,  p_l1w1);
    cudaGetSymbolAddress((void**)&lw12,  p_l1w2);
    cudaGetSymbolAddress((void**)&lw21,  p_l2w1);
    cudaGetSymbolAddress((void**)&lw22,  p_l2w2);

    cudaFuncSetAttribute(gemm_p<0>, cudaFuncAttributeMaxDynamicSharedMemorySize, SMEM_DYN);
    cudaFuncSetAttribute(gemm_p<1>, cudaFuncAttributeMaxDynamicSharedMemorySize, SMEM_DYN);
    cudaFuncSetAttribute(gemm_p<2>, cudaFuncAttributeMaxDynamicSharedMemorySize, SMEM_DYN);
    cudaFuncSetAttribute(gemm_p<3>, cudaFuncAttributeMaxDynamicSharedMemorySize, SMEM_DYN);

    auto pk = [&](const float* src, uint32_t* dst, ll n, int C, bool relu) {
        const int n4 = (int)(n >> 2);
        const int gr = (n4 + 255) / 256;
        if (relu) pack_k<true ><<<gr, 256>>>(src, dst, C, n4);
        else      pack_k<false><<<gr, 256>>>(src, dst, C, n4);
    };

    const ll DS  = (ll)DD * SS;
    const ll DM  = (ll)DD * MIDD;
    const ll SD  = (ll)SS * DD;
    const ll WSZ = (ll)HH * 3 * MIDD * SS;
    const ll HSD = (ll)HH * SS * DD;

    // ---- packing of inputs & weights ----
    pt_k<<<(int)((SS * (DD / 2) + 255) / 256), 256>>>(inp, pinpT, DD, SS);
    pk(enc_k,  penck, DS, SS, true);
    pk(enc_v,  pencv, DS, SS, true);
    pk(w_qkv1, pw1,   3ll * DD * DD, DD, false);
    pk(w_qkv2, pw2,   (ll)DD * DD,   DD, false);
    pk(mh1_W1, W1a,   WSZ, SS,   false);
    pk(mh1_W2, W2a,   WSZ, MIDD, false);
    pk(mh2_W1, W1b,   WSZ, SS,   false);
    pk(mh2_W2, W2b,   WSZ, MIDD, false);
    pk(c1_w1,  c1a,   (ll)MIDD * HH * DD, HH * DD, false);
    pk(c2_w1,  c2a,   (ll)MIDD * HH * DD, HH * DD, false);
    pk(c1_w2,  c1b,   (ll)DD * MIDD, MIDD, false);
    pk(c2_w2,  c2b,   (ll)DD * MIDD, MIDD, false);
    pk(l1_w1,  lw11,  (ll)MIDD * SS,   SS,   false);
    pk(l1_w2,  lw12,  (ll)SOUT * MIDD, MIDD, false);
    pk(l2_w1,  lw21,  (ll)MIDD * SOUT, SOUT, false);
    pk(l2_w2,  lw22,  (ll)SOUT * MIDD, MIDD, false);

    auto run_block = [&](const uint32_t* qp0, const uint32_t* qp1, const uint32_t* qp2,
                         const uint32_t* W1, const uint32_t* W2,
                         const uint32_t* cw1, const uint32_t* cw2) {
        const uint32_t* qp[3] = {qp0, qp1, qp2};
        for (int q = 0; q < 3; q++) {
            // z[h] = relu(qkv[q]) @ W1[h,q]^T  (D, MID) packed+relu
            gemm_p<3><<<dim3(MIDD / 128, DD / 128, HH), 256, SMEM_DYN>>>(
                qp[q], W1 + (ll)q * MIDD * SS, z,
                DD, MIDD, SS, 0, 3ll * MIDD * SS, DM, MIDD);
            if (q < 2) {
                // swapped: s{q}T[s'][d] = sum_m W2[h,q][s'][m] * z[d][m]  (S, D)
                gemm_p<2><<<dim3(DD / 128, SS / 128, HH), 256, SMEM_DYN>>>(
                    W2 + (ll)q * SS * MIDD, z, s + (ll)q * HSD,
                    SS, DD, MIDD, 3ll * SS * MIDD, DM, SD, DD);
            } else {
                // sv[d][s'] = sum_m z[d][m] * W2[h,2][s'][m]  (D, S)
                gemm_p<2><<<dim3(SS / 128, DD / 128, HH), 256, SMEM_DYN>>>(
                    z, W2 + 2ll * SS * MIDD, s + 2ll * HSD,
                    DD, SS, MIDD, DM, 3ll * SS * MIDD, DS, SS);
            }
        }
        // bT[t][s'] = sum_d sqT[t][d] * skT[s'][d]   (S, S)
        gemm_p<2><<<dim3(SS / 128, SS / 128, HH), 256, SMEM_DYN>>>(
            s, s + HSD, bm, SS, SS, DD, SD, SD, (ll)SS * SS, SS);
        // attT[t][h*D+d] = sum_s bT[t][s] * sv[d][s]  -> packed+relu, ldC = H*D
        gemm_p<3><<<dim3(DD / 128, SS / 128, HH), 256, SMEM_DYN>>>(
            bm, s + 2ll * HSD, att, SS, DD, SS, (ll)SS * SS, DS, (ll)DD, HH * DD);
        // y[s'][m] = sum_c relu(attT)[s'][c] * cw1[m][c]  (S, MID) packed+relu
        gemm_p<3><<<dim3(MIDD / 128, SS / 128, 1), 256, SMEM_DYN>>>(
            att, cw1, y, SS, MIDD, HH * DD, 0, 0, 0, MIDD);
        // m[d][s'] = sum_m cw2[d][m] * relu(y)[s'][m]  fp32
        gemm_p<0><<<dim3(SS / 128, DD / 128, 1), 256, SMEM_DYN>>>(
            cw2, y, mb, DD, SS, MIDD, 0, 0, 0, SS);
    };

    // qkv1[q][d][s'] = sum_j w_qkv1[q][d][j] * inpT[s'][j]  packed+relu
    gemm_p<3><<<dim3(SS / 128, DD / 128, 3), 256, SMEM_DYN>>>(
        pw1, pinpT, qkv, DD, SS, DD, (ll)DD * DD, 0, DS, SS);

    run_block(qkv, qkv + DS, qkv + 2ll * DS, W1a, W2a, c1a, c1b);
    add_ln_k<0><<<DD, 256>>>(inp, mb, gamma, beta, hf);             // h1 fp32
    pt_k<<<(int)((SS * (DD / 2) + 255) / 256), 256>>>(hf, h1t, DD, SS);

    // q2[d][s'] = sum_j w_qkv2[0][d][j] * h1T[s'][j]  packed+relu
    gemm_p<3><<<dim3(SS / 128, DD / 128, 1), 256, SMEM_DYN>>>(
        pw2, h1t, qkv, DD, SS, DD, 0, 0, 0, SS);

    run_block(qkv, penck, pencv, W1b, W2b, c2a, c2b);
    add_ln_k<2><<<DD, 256>>>(inp, mb, gamma, beta, hb);             // h2 packed+relu

    // x1 = relu(h2) @ l1_w1^T  (D, MID)
    gemm_p<3><<<dim3(MIDD / 128, DD / 128, 1), 256, SMEM_DYN>>>(
        hb, lw11, x1, DD, MIDD, SS, 0, 0, 0, MIDD);
    // x2 = relu(x1) @ l1_w2^T  (D, SOUT)
    gemm_p<3><<<dim3(SOUT / 128, DD / 128, 1), 256, SMEM_DYN>>>(
        x1, lw12, x2, DD, SOUT, MIDD, 0, 0, 0, SOUT);
    // y1 = relu(x2) @ l2_w1^T  (D, MID)
    gemm_p<3><<<dim3(MIDD / 128, DD / 128, 1), 256, SMEM_DYN>>>(
        x2, lw21, x1, DD, MIDD, SOUT, 0, 0, 0, MIDD);
    // out = tanh(relu(y1) @ l2_w2^T)  fp32
    gemm_p<1><<<dim3(SOUT / 128, DD / 128, 1), 256, SMEM_DYN>>>(
        x1, lw22, out, DD, SOUT, MIDD, 0, 0, 0, SOUT);
}

// round 13
// speedup vs baseline: 1.0366x; 1.0366x over previous
#include <cuda_runtime.h>
#include <cstdint>

#define HH 8
#define DD 1024
#define SS 1024
#define MIDD 2048
#define SOUT 512

typedef long long ll;

// ---------------- scratch (device globals; no allocation allowed) ----------
// packed arrays: per row, word 2p = bf16x2 hi-pair of elements (2p,2p+1),
// word 2p+1 = bf16x2 lo-pair (residuals). Word c <-> element c addressing.
__device__ uint32_t p_qkv[3ll * DD * SS];              // (d, s) per q
__device__ uint32_t p_z[(ll)HH * DD * MIDD];           // (d, m) per h
__device__ uint32_t p_s[3ll * HH * SS * DD];           // sqT (s,d), skT (s,d), sv (d,s)
__device__ uint32_t p_bm[(ll)HH * SS * SS];            // bT (t, s) per h
__device__ uint32_t p_att[(ll)SS * HH * DD];           // attT (t, h*D+d)
__device__ uint32_t p_y[(ll)SS * MIDD];                // (s, m)
__device__ uint32_t p_h[(ll)DD * SS];                  // h2 packed (d, s)
__device__ uint32_t p_h1t[(ll)SS * DD];                // h1T packed (s, d)
__device__ uint32_t p_x1[(ll)DD * MIDD];
__device__ uint32_t p_x2[(ll)DD * SOUT];
__device__ float    g_m [(ll)DD * SS];                 // fp32 mha out
__device__ float    g_hf[(ll)DD * SS];                 // fp32 h1
// packed inputs / weights
__device__ uint32_t p_inpT[(ll)SS * DD];               // inp transposed (s, d)
__device__ uint32_t p_enck[(ll)DD * SS];
__device__ uint32_t p_encv[(ll)DD * SS];
__device__ uint32_t p_wqkv1[3ll * DD * DD];
__device__ uint32_t p_wqkv2[(ll)DD * DD];
__device__ uint32_t p_W1a[(ll)HH * 3 * MIDD * SS];
__device__ uint32_t p_W2a[(ll)HH * 3 * SS * MIDD];
__device__ uint32_t p_W1b[(ll)HH * 3 * MIDD * SS];
__device__ uint32_t p_W2b[(ll)HH * 3 * SS * MIDD];
__device__ uint32_t p_c1w1[(ll)MIDD * HH * DD];
__device__ uint32_t p_c2w1[(ll)MIDD * HH * DD];
__device__ uint32_t p_c1w2[(ll)DD * MIDD];
__device__ uint32_t p_c2w2[(ll)DD * MIDD];
__device__ uint32_t p_l1w1[(ll)MIDD * SS];
__device__ uint32_t p_l1w2[(ll)SOUT * MIDD];
__device__ uint32_t p_l2w1[(ll)MIDD * SOUT];
__device__ uint32_t p_l2w2[(ll)SOUT * MIDD];

// ---------------- PTX helpers (base sm_103 features only) -------------------
__device__ __forceinline__ uint32_t smem_u32(const void* p) {
    uint32_t a;
    asm("{ .reg .u64 t; cvta.to.shared.u64 t, %1; cvt.u32.u64 %0, t; }"
        : "=r"(a) : "l"(p));
    return a;
}
__device__ __forceinline__ void cpa16(uint32_t dst, const void* src) {
    asm volatile("cp.async.cg.shared.global [%0], [%1], 16;"
                 :: "r"(dst), "l"(src) : "memory");
}
__device__ __forceinline__ void cp_commit() {
    asm volatile("cp.async.commit_group;" ::: "memory");
}
template<int NG>
__device__ __forceinline__ void cp_wait() {
    asm volatile("cp.async.wait_group %0;" :: "n"(NG) : "memory");
}

// two-term bf16 split of an element pair -> hi-pair word, lo-pair word
template<bool RELU>
__device__ __forceinline__ void pack2(float2 v, uint32_t& hi, uint32_t& lo) {
    if (RELU) { v.x = fmaxf(v.x, 0.f); v.y = fmaxf(v.y, 0.f); }
    asm("cvt.rn.bf16x2.f32 %0, %1, %2;" : "=r"(hi) : "f"(v.y), "f"(v.x));
    const float hx = __uint_as_float(hi << 16);
    const float hy = __uint_as_float(hi & 0xffff0000u);
    asm("cvt.rn.bf16x2.f32 %0, %1, %2;" : "=r"(lo) : "f"(v.y - hy), "f"(v.x - hx));
}

__device__ __forceinline__ void mma16(float* d, const uint32_t* a, const uint32_t* b) {
    asm volatile(
        "mma.sync.aligned.m16n8k16.row.col.f32.bf16.bf16.f32 "
        "{%0,%1,%2,%3}, {%4,%5,%6,%7}, {%8,%9}, {%0,%1,%2,%3};"
        : "+f"(d[0]), "+f"(d[1]), "+f"(d[2]), "+f"(d[3])
        : "r"(a[0]), "r"(a[1]), "r"(a[2]), "r"(a[3]), "r"(b[0]), "r"(b[1]));
}

// ---------------- pack kernels ----------------------------------------------
// row-major pack: fp32 X[R][C] -> packed same shape (pairs along C, linear)
template<bool RELU>
__global__ __launch_bounds__(256) void pack_k(
    const float* __restrict__ src, uint32_t* __restrict__ dst, int n4)
{
    const int i = blockIdx.x * 256 + threadIdx.x;
    if (i >= n4) return;
    const ll idx = (ll)i * 4;
    const float4 v = *(const float4*)(src + idx);
    uint4 o;
    pack2<RELU>(make_float2(v.x, v.y), o.x, o.y);
    pack2<RELU>(make_float2(v.z, v.w), o.z, o.w);
    *(uint4*)(dst + idx) = o;
}

// transpose-pack: fp32 X[R][C] -> packed Y[C][R], pairs along R
__global__ __launch_bounds__(256) void pt_k(
    const float* __restrict__ X, uint32_t* __restrict__ Y, int R, int C)
{
    const int i = blockIdx.x * 256 + threadIdx.x;
    const int total = C * (R >> 1);
    if (i >= total) return;
    const int c = i % C;
    const int p = i / C;
    const float f0 = X[(ll)(2 * p) * C + c];
    const float f1 = X[(ll)(2 * p + 1) * C + c];
    uint2 w;
    pack2<false>(make_float2(f0, f1), w.x, w.y);
    *(uint2*)(Y + (ll)c * R + 2 * p) = w;
}

// ---------------- packed bf16x3 mma.sync GEMM (row-major x row-major) -------
// D[m][n] = sum_k a[m][k] * b[n][k]; operands in linear hi/lo pair layout.
//   EP: 0 = fp32 out, 1 = fp32 tanh out, 2 = packed out, 3 = packed+relu out.
// M,N mult of 128; K mult of 32. 256 threads (8 warps, 2x4 warp grid).

#define STR     40
#define TILE_W  (128 * STR)
#define STAGE_B (TILE_W * 4)
#define SMEM_DYN (4 * STAGE_B)

template<int EP>
__global__ __launch_bounds__(256, 2) void gemm_p(
    const uint32_t* __restrict__ Ag, const uint32_t* __restrict__ Bg, void* Cg,
    int M, int N, int K, ll sA, ll sB, ll sC, int ldC)
{
    extern __shared__ __align__(16) uint32_t smem[];
    const uint32_t sb = smem_u32(smem);

    const uint32_t* A = Ag + (ll)blockIdx.z * sA;
    const uint32_t* B = Bg + (ll)blockIdx.z * sB;
    const int m0 = blockIdx.y * 128;
    const int n0 = blockIdx.x * 128;

    const int tid = threadIdx.x;
    const int wid = tid >> 5, lid = tid & 31;
    const int wm = wid >> 2, wn = wid & 3;
    const int g = lid >> 2, tg = lid & 3;

    float acc[4][4][4];
    #pragma unroll
    for (int mi = 0; mi < 4; mi++)
        #pragma unroll
        for (int ni = 0; ni < 4; ni++)
            #pragma unroll
            for (int r = 0; r < 4; r++) acc[mi][ni][r] = 0.f;

    auto issue = [&](int t) {
        const int st = t & 1;
        const uint32_t abase = sb + (uint32_t)(st * 2) * STAGE_B;
        const uint32_t bbase = abase + STAGE_B;
        const int k0 = t << 5;
        #pragma unroll
        for (int i = 0; i < 4; i++) {
            int idx = tid + i * 256;
            int r = idx >> 3, kq = (idx & 7) << 2;
            cpa16(abase + (uint32_t)(r * STR + kq) * 4,
                  A + (ll)(m0 + r) * K + k0 + kq);
        }
        #pragma unroll
        for (int i = 0; i < 4; i++) {
            int idx = tid + i * 256;
            int r = idx >> 3, kq = (idx & 7) << 2;
            cpa16(bbase + (uint32_t)(r * STR + kq) * 4,
                  B + (ll)(n0 + r) * K + k0 + kq);
        }
    };

    const int T = K >> 5;
    issue(0);
    cp_commit();

    for (int t = 0; t < T; t++) {
        if (t + 1 < T) { issue(t + 1); cp_commit(); cp_wait<1>(); }
        else           { cp_wait<0>(); }
        __syncthreads();

        const uint32_t* As = smem + (t & 1) * 2 * TILE_W;
        const uint32_t* Bs = As + TILE_W;

        #pragma unroll
        for (int ks = 0; ks < 2; ks++) {
            const int kb = ks * 16;
            uint2 b0[4], b1[4];
            #pragma unroll
            for (int ni = 0; ni < 4; ni++) {
                const uint32_t* p = Bs + (wn * 32 + ni * 8 + g) * STR + kb + 2 * tg;
                b0[ni] = *(const uint2*)p;
                b1[ni] = *(const uint2*)(p + 8);
            }
            #pragma unroll
            for (int mi = 0; mi < 4; mi++) {
                const uint32_t* pa = As + (wm * 64 + mi * 16 + g) * STR + kb + 2 * tg;
                const uint2 a00 = *(const uint2*)pa;
                const uint2 a01 = *(const uint2*)(pa + 8);
                const uint2 a10 = *(const uint2*)(pa + 8 * STR);
                const uint2 a11 = *(const uint2*)(pa + 8 * STR + 8);
                uint32_t ah[4] = {a00.x, a10.x, a01.x, a11.x};
                uint32_t al[4] = {a00.y, a10.y, a01.y, a11.y};
                #pragma unroll
                for (int ni = 0; ni < 4; ni++) {
                    uint32_t bh[2] = {b0[ni].x, b1[ni].x};
                    uint32_t bl[2] = {b0[ni].y, b1[ni].y};
                    mma16(acc[mi][ni], ah, bh);
                    mma16(acc[mi][ni], ah, bl);
                    mma16(acc[mi][ni], al, bh);
                }
            }
        }
        __syncthreads();
    }

    // ---- epilogue ----
    #pragma unroll
    for (int mi = 0; mi < 4; mi++) {
        #pragma unroll
        for (int ni = 0; ni < 4; ni++) {
            const int r0 = m0 + wm * 64 + mi * 16 + g;
            const int c  = n0 + wn * 32 + ni * 8 + 2 * tg;
            float2 v0 = make_float2(acc[mi][ni][0], acc[mi][ni][1]);
            float2 v1 = make_float2(acc[mi][ni][2], acc[mi][ni][3]);
            if (EP <= 1) {
                float* C = (float*)Cg + (ll)blockIdx.z * sC;
                if (EP == 1) {
                    v0.x = tanhf(v0.x); v0.y = tanhf(v0.y);
                    v1.x = tanhf(v1.x); v1.y = tanhf(v1.y);
                }
                *(float2*)(C + (ll)r0 * ldC + c)       = v0;
                *(float2*)(C + (ll)(r0 + 8) * ldC + c) = v1;
            } else {
                uint32_t* C = (uint32_t*)Cg + (ll)blockIdx.z * sC;
                uint2 w0, w1;
                pack2<EP == 3>(v0, w0.x, w0.y);
                pack2<EP == 3>(v1, w1.x, w1.y);
                *(uint2*)(C + (ll)r0 * ldC + c)       = w0;
                *(uint2*)(C + (ll)(r0 + 8) * ldC + c) = w1;
            }
        }
    }
}

// ---------------- fused residual-add + LayerNorm -----------------------------
// OM: 0 = fp32 out, 2 = packed+relu out
template<int OM>
__global__ __launch_bounds__(256) void add_ln_k(
    const float* __restrict__ x, const float* __restrict__ m,
    const float* __restrict__ g, const float* __restrict__ b,
    void* __restrict__ o)
{
    const int row = blockIdx.x;
    const ll off = (ll)row * SS;
    float2 v[2];
    float sum = 0.f, sq = 0.f;
    #pragma unroll
    for (int j = 0; j < 2; j++) {
        int i2 = threadIdx.x * 2 + j * 512;
        float2 xv = *(const float2*)(x + off + i2);
        float2 mv = *(const float2*)(m + off + i2);
        v[j] = make_float2(xv.x + mv.x, xv.y + mv.y);
        sum += v[j].x + v[j].y;
        sq  += v[j].x * v[j].x + v[j].y * v[j].y;
    }
    #pragma unroll
    for (int o2 = 16; o2; o2 >>= 1) {
        sum += __shfl_xor_sync(0xffffffffu, sum, o2);
        sq  += __shfl_xor_sync(0xffffffffu, sq,  o2);
    }
    __shared__ float rs[8], rq[8];
    const int w = threadIdx.x >> 5, l = threadIdx.x & 31;
    if (l == 0) { rs[w] = sum; rq[w] = sq; }
    __syncthreads();
    if (w == 0) {
        float s2 = (l < 8) ? rs[l] : 0.f;
        float q2 = (l < 8) ? rq[l] : 0.f;
        #pragma unroll
        for (int o2 = 4; o2; o2 >>= 1) {
            s2 += __shfl_xor_sync(0xffffffffu, s2, o2);
            q2 += __shfl_xor_sync(0xffffffffu, q2, o2);
        }
        if (l == 0) { rs[0] = s2; rq[0] = q2; }
    }
    __syncthreads();
    const float mu  = rs[0] * (1.f / SS);
    const float var = rq[0] * (1.f / SS) - mu * mu;
    const float inv = rsqrtf(var + 1e-6f);
    #pragma unroll
    for (int j = 0; j < 2; j++) {
        int i2 = threadIdx.x * 2 + j * 512;
        float2 gv = *(const float2*)(g + i2);
        float2 bv = *(const float2*)(b + i2);
        float2 t = make_float2((v[j].x - mu) * inv * gv.x + bv.x,
                               (v[j].y - mu) * inv * gv.y + bv.y);
        if (OM == 0) {
            *(float2*)((float*)o + off + i2) = t;
        } else {
            uint2 wo;
            pack2<true>(t, wo.x, wo.y);
            *(uint2*)((uint32_t*)o + off + i2) = wo;
        }
    }
}

// ---------------- host orchestration ----------------------------------------
extern "C" void kernel_launch(void* const* d_in, const int* in_sizes, int n_in,
                              void* d_out, int out_size)
{
    const float* inp    = (const float*)d_in[0];
    const float* enc_k  = (const float*)d_in[1];
    const float* enc_v  = (const float*)d_in[2];
    const float* w_qkv1 = (const float*)d_in[3];
    const float* w_qkv2 = (const float*)d_in[4];
    const float* mh1_W1 = (const float*)d_in[5];
    const float* mh1_W2 = (const float*)d_in[6];
    const float* mh2_W1 = (const float*)d_in[7];
    const float* mh2_W2 = (const float*)d_in[8];
    const float* c1_w1  = (const float*)d_in[9];
    const float* c1_w2  = (const float*)d_in[10];
    const float* c2_w1  = (const float*)d_in[11];
    const float* c2_w2  = (const float*)d_in[12];
    const float* l1_w1  = (const float*)d_in[13];
    const float* l1_w2  = (const float*)d_in[14];
    const float* l2_w1  = (const float*)d_in[15];
    const float* l2_w2  = (const float*)d_in[16];
    const float* gamma  = (const float*)d_in[17];
    const float* beta   = (const float*)d_in[18];
    float* out = (float*)d_out;

    uint32_t *qkv, *z, *s, *bm, *att, *y, *hb, *h1t, *x1, *x2;
    uint32_t *pinpT, *penck, *pencv, *pw1, *pw2;
    uint32_t *W1a, *W2a, *W1b, *W2b, *c1a, *c2a, *c1b, *c2b;
    uint32_t *lw11, *lw12, *lw21, *lw22;
    float *mb, *hf;
    cudaGetSymbolAddress((void**)&qkv,  p_qkv);
    cudaGetSymbolAddress((void**)&z,    p_z);
    cudaGetSymbolAddress((void**)&s,    p_s);
    cudaGetSymbolAddress((void**)&bm,   p_bm);
    cudaGetSymbolAddress((void**)&att,  p_att);
    cudaGetSymbolAddress((void**)&y,    p_y);
    cudaGetSymbolAddress((void**)&hb,   p_h);
    cudaGetSymbolAddress((void**)&h1t,  p_h1t);
    cudaGetSymbolAddress((void**)&x1,   p_x1);
    cudaGetSymbolAddress((void**)&x2,   p_x2);
    cudaGetSymbolAddress((void**)&mb,   g_m);
    cudaGetSymbolAddress((void**)&hf,   g_hf);
    cudaGetSymbolAddress((void**)&pinpT, p_inpT);
    cudaGetSymbolAddress((void**)&penck, p_enck);
    cudaGetSymbolAddress((void**)&pencv, p_encv);
    cudaGetSymbolAddress((void**)&pw1,   p_wqkv1);
    cudaGetSymbolAddress((void**)&pw2,   p_wqkv2);
    cudaGetSymbolAddress((void**)&W1a,   p_W1a);
    cudaGetSymbolAddress((void**)&W2a,   p_W2a);
    cudaGetSymbolAddress((void**)&W1b,   p_W1b);
    cudaGetSymbolAddress((void**)&W2b,   p_W2b);
    cudaGetSymbolAddress((void**)&c1a,   p_c1w1);
    cudaGetSymbolAddress((void**)&c2a,   p_c2w1);
    cudaGetSymbolAddress((void**)&c1b,   p_c1w2);
    cudaGetSymbolAddress((void**)&c2b,   p_c2w2);
    cudaGetSymbolAddress((void**)&lw11,  p_l1w1);
    cudaGetSymbolAddress((void**)&lw12,  p_l1w2);
    cudaGetSymbolAddress((void**)&lw21,  p_l2w1);
    cudaGetSymbolAddress((void**)&lw22,  p_l2w2);

    cudaFuncSetAttribute(gemm_p<0>, cudaFuncAttributeMaxDynamicSharedMemorySize, SMEM_DYN);
    cudaFuncSetAttribute(gemm_p<1>, cudaFuncAttributeMaxDynamicSharedMemorySize, SMEM_DYN);
    cudaFuncSetAttribute(gemm_p<2>, cudaFuncAttributeMaxDynamicSharedMemorySize, SMEM_DYN);
    cudaFuncSetAttribute(gemm_p<3>, cudaFuncAttributeMaxDynamicSharedMemorySize, SMEM_DYN);

    auto pk = [&](const float* src, uint32_t* dst, ll n, bool relu) {
        const int n4 = (int)(n >> 2);
        const int gr = (n4 + 255) / 256;
        if (relu) pack_k<true ><<<gr, 256>>>(src, dst, n4);
        else      pack_k<false><<<gr, 256>>>(src, dst, n4);
    };

    const ll DS  = (ll)DD * SS;
    const ll DM  = (ll)DD * MIDD;
    const ll SD  = (ll)SS * DD;
    const ll WSZ = (ll)HH * 3 * MIDD * SS;
    const ll HSD = (ll)HH * SS * DD;

    // ---- packing of inputs & weights ----
    pt_k<<<(int)((SS * (DD / 2) + 255) / 256), 256>>>(inp, pinpT, DD, SS);
    pk(enc_k,  penck, DS, true);
    pk(enc_v,  pencv, DS, true);
    pk(w_qkv1, pw1,   3ll * DD * DD, false);
    pk(w_qkv2, pw2,   (ll)DD * DD,   false);
    pk(mh1_W1, W1a,   WSZ, false);
    pk(mh1_W2, W2a,   WSZ, false);
    pk(mh2_W1, W1b,   WSZ, false);
    pk(mh2_W2, W2b,   WSZ, false);
    pk(c1_w1,  c1a,   (ll)MIDD * HH * DD, false);
    pk(c2_w1,  c2a,   (ll)MIDD * HH * DD, false);
    pk(c1_w2,  c1b,   (ll)DD * MIDD, false);
    pk(c2_w2,  c2b,   (ll)DD * MIDD, false);
    pk(l1_w1,  lw11,  (ll)MIDD * SS,   false);
    pk(l1_w2,  lw12,  (ll)SOUT * MIDD, false);
    pk(l2_w1,  lw21,  (ll)MIDD * SOUT, false);
    pk(l2_w2,  lw22,  (ll)SOUT * MIDD, false);

    auto run_block = [&](const uint32_t* qp0, const uint32_t* qp1, const uint32_t* qp2,
                         const uint32_t* W1, const uint32_t* W2,
                         const uint32_t* cw1, const uint32_t* cw2) {
        const uint32_t* qp[3] = {qp0, qp1, qp2};
        for (int q = 0; q < 3; q++) {
            // z[h] = relu(qkv[q]) @ W1[h,q]^T  (D, MID) packed+relu
            gemm_p<3><<<dim3(MIDD / 128, DD / 128, HH), 256, SMEM_DYN>>>(
                qp[q], W1 + (ll)q * MIDD * SS, z,
                DD, MIDD, SS, 0, 3ll * MIDD * SS, DM, MIDD);
            if (q < 2) {
                // swapped: s{q}T[s'][d] = sum_m W2[h,q][s'][m] * z[d][m]  (S, D)
                gemm_p<2><<<dim3(DD / 128, SS / 128, HH), 256, SMEM_DYN>>>(
                    W2 + (ll)q * SS * MIDD, z, s + (ll)q * HSD,
                    SS, DD, MIDD, 3ll * SS * MIDD, DM, SD, DD);
            } else {
                // sv[d][s'] = sum_m z[d][m] * W2[h,2][s'][m]  (D, S)
                gemm_p<2><<<dim3(SS / 128, DD / 128, HH), 256, SMEM_DYN>>>(
                    z, W2 + 2ll * SS * MIDD, s + 2ll * HSD,
                    DD, SS, MIDD, DM, 3ll * SS * MIDD, DS, SS);
            }
        }
        // bT[t][s'] = sum_d sqT[t][d] * skT[s'][d]   (S, S)
        gemm_p<2><<<dim3(SS / 128, SS / 128, HH), 256, SMEM_DYN>>>(
            s, s + HSD, bm, SS, SS, DD, SD, SD, (ll)SS * SS, SS);
        // attT[t][h*D+d] = sum_s bT[t][s] * sv[d][s]  -> packed+relu, ldC = H*D
        gemm_p<3><<<dim3(DD / 128, SS / 128, HH), 256, SMEM_DYN>>>(
            bm, s + 2ll * HSD, att, SS, DD, SS, (ll)SS * SS, DS, (ll)DD, HH * DD);
        // y[s'][m] = sum_c relu(attT)[s'][c] * cw1[m][c]  (S, MID) packed+relu
        gemm_p<3><<<dim3(MIDD / 128, SS / 128, 1), 256, SMEM_DYN>>>(
            att, cw1, y, SS, MIDD, HH * DD, 0, 0, 0, MIDD);
        // m[d][s'] = sum_m cw2[d][m] * relu(y)[s'][m]  fp32
        gemm_p<0><<<dim3(SS / 128, DD / 128, 1), 256, SMEM_DYN>>>(
            cw2, y, mb, DD, SS, MIDD, 0, 0, 0, SS);
    };

    // qkv1[q][d][s'] = sum_j w_qkv1[q][d][j] * inpT[s'][j]  packed+relu
    gemm_p<3><<<dim3(SS / 128, DD / 128, 3), 256, SMEM_DYN>>>(
        pw1, pinpT, qkv, DD, SS, DD, (ll)DD * DD, 0, DS, SS);

    run_block(qkv, qkv + DS, qkv + 2ll * DS, W1a, W2a, c1a, c1b);
    add_ln_k<0><<<DD, 256>>>(inp, mb, gamma, beta, hf);             // h1 fp32
    pt_k<<<(int)((SS * (DD / 2) + 255) / 256), 256>>>(hf, h1t, DD, SS);

    // q2[d][s'] = sum_j w_qkv2[0][d][j] * h1T[s'][j]  packed+relu
    gemm_p<3><<<dim3(SS / 128, DD / 128, 1), 256, SMEM_DYN>>>(
        pw2, h1t, qkv, DD, SS, DD, 0, 0, 0, SS);

    run_block(qkv, penck, pencv, W1b, W2b, c2a, c2b);
    add_ln_k<2><<<DD, 256>>>(inp, mb, gamma, beta, hb);             // h2 packed+relu

    // x1 = relu(h2) @ l1_w1^T  (D, MID)
    gemm_p<3><<<dim3(MIDD / 128, DD / 128, 1), 256, SMEM_DYN>>>(
        hb, lw11, x1, DD, MIDD, SS, 0, 0, 0, MIDD);
    // x2 = relu(x1) @ l1_w2^T  (D, SOUT)
    gemm_p<3><<<dim3(SOUT / 128, DD / 128, 1), 256, SMEM_DYN>>>(
        x1, lw12, x2, DD, SOUT, MIDD, 0, 0, 0, SOUT);
    // y1 = relu(x2) @ l2_w1^T  (D, MID)
    gemm_p<3><<<dim3(MIDD / 128, DD / 128, 1), 256, SMEM_DYN>>>(
        x2, lw21, x1, DD, MIDD, SOUT, 0, 0, 0, MIDD);
    // out = tanh(relu(y1) @ l2_w2^T)  fp32
    gemm_p<1><<<dim3(SOUT / 128, DD / 128, 1), 256, SMEM_DYN>>>(
        x1, lw22, out, DD, SOUT, MIDD, 0, 0, 0, SOUT);
}

// round 14
// speedup vs baseline: 1.1699x; 1.1286x over previous
#include <cuda_runtime.h>
#include <cstdint>

#define HH 8
#define DD 1024
#define SS 1024
#define MIDD 2048
#define SOUT 512

typedef long long ll;

// ---------------- scratch (device globals; no allocation allowed) ----------
// packed format: one uint32 per element = (lo_bf16 << 16) | hi_bf16
__device__ uint32_t p_qkv [3ll * DD * SS];             // block1 q-operands (q,d,s)
__device__ uint32_t p_qkv2[3ll * DD * SS];             // block2: q2, enc_k, enc_v
__device__ uint32_t p_z[3ll * HH * DD * MIDD];         // (q,h,d,m)
__device__ uint32_t p_s[(ll)HH * 3 * DD * SS];         // (h,q,d,s)
__device__ uint32_t p_bm[(ll)HH * SS * SS];
__device__ uint32_t p_att[(ll)HH * DD * SS];           // (h,d,t)
__device__ uint32_t p_y[(ll)SS * MIDD];
__device__ uint32_t p_h[(ll)DD * SS];
__device__ uint32_t p_x1[(ll)DD * MIDD];
__device__ uint32_t p_x2[(ll)DD * SOUT];
__device__ float    g_m[(ll)DD * SS];
// packed inputs / weights
__device__ uint32_t p_inp [(ll)DD * SS];
__device__ uint32_t p_wqkv1[3ll * DD * DD];
__device__ uint32_t p_wqkv2[(ll)DD * DD];
__device__ uint32_t p_W1a[(ll)HH * 3 * MIDD * SS];
__device__ uint32_t p_W2a[(ll)HH * 3 * SS * MIDD];
__device__ uint32_t p_W1b[(ll)HH * 3 * MIDD * SS];
__device__ uint32_t p_W2b[(ll)HH * 3 * SS * MIDD];
__device__ uint32_t p_c1w1[(ll)MIDD * HH * DD];
__device__ uint32_t p_c2w1[(ll)MIDD * HH * DD];
__device__ uint32_t p_c1w2[(ll)DD * MIDD];
__device__ uint32_t p_c2w2[(ll)DD * MIDD];
__device__ uint32_t p_l1w1[(ll)MIDD * SS];
__device__ uint32_t p_l1w2[(ll)SOUT * MIDD];
__device__ uint32_t p_l2w1[(ll)MIDD * SOUT];
__device__ uint32_t p_l2w2[(ll)SOUT * MIDD];

// ---------------- PTX helpers (base sm_103 features only) -------------------
__device__ __forceinline__ uint32_t smem_u32(const void* p) {
    uint32_t a;
    asm("{ .reg .u64 t; cvta.to.shared.u64 t, %1; cvt.u32.u64 %0, t; }"
        : "=r"(a) : "l"(p));
    return a;
}
__device__ __forceinline__ void cpa16(uint32_t dst, const void* src) {
    asm volatile("cp.async.cg.shared.global [%0], [%1], 16;"
                 :: "r"(dst), "l"(src) : "memory");
}
__device__ __forceinline__ void cpa4(uint32_t dst, const void* src) {
    asm volatile("cp.async.ca.shared.global [%0], [%1], 4;"
                 :: "r"(dst), "l"(src) : "memory");
}
__device__ __forceinline__ void cp_commit() {
    asm volatile("cp.async.commit_group;" ::: "memory");
}
template<int NG>
__device__ __forceinline__ void cp_wait() {
    asm volatile("cp.async.wait_group %0;" :: "n"(NG) : "memory");
}
__device__ __forceinline__ uint32_t prmtb(uint32_t a, uint32_t b, uint32_t s) {
    uint32_t r;
    asm("prmt.b32 %0, %1, %2, %3;" : "=r"(r) : "r"(a), "r"(b), "r"(s));
    return r;
}

// pack two floats -> two packed element words (lo<<16|hi each)
template<bool RELU>
__device__ __forceinline__ void pack2(float2 v, uint32_t& w0, uint32_t& w1) {
    if (RELU) { v.x = fmaxf(v.x, 0.f); v.y = fmaxf(v.y, 0.f); }
    uint32_t hp, lp;
    asm("cvt.rn.bf16x2.f32 %0, %1, %2;" : "=r"(hp) : "f"(v.y), "f"(v.x));
    const float hx = __uint_as_float(hp << 16);
    const float hy = __uint_as_float(hp & 0xffff0000u);
    asm("cvt.rn.bf16x2.f32 %0, %1, %2;" : "=r"(lp) : "f"(v.y - hy), "f"(v.x - hx));
    w0 = prmtb(hp, lp, 0x5410);
    w1 = prmtb(hp, lp, 0x7632);
}

// unpack two consecutive packed elems -> bf16x2 hi-pair + lo-pair (2 PRMT)
__device__ __forceinline__ void fragp(const uint32_t* p, uint32_t& hi, uint32_t& lo) {
    const uint2 e = *(const uint2*)p;
    hi = prmtb(e.x, e.y, 0x5410);
    lo = prmtb(e.x, e.y, 0x7632);
}

__device__ __forceinline__ void mma16(float* d, const uint32_t* a, const uint32_t* b) {
    asm volatile(
        "mma.sync.aligned.m16n8k16.row.col.f32.bf16.bf16.f32 "
        "{%0,%1,%2,%3}, {%4,%5,%6,%7}, {%8,%9}, {%0,%1,%2,%3};"
        : "+f"(d[0]), "+f"(d[1]), "+f"(d[2]), "+f"(d[3])
        : "r"(a[0]), "r"(a[1]), "r"(a[2]), "r"(a[3]), "r"(b[0]), "r"(b[1]));
}

// ---------------- elementwise pack kernel (ILP=4) ----------------------------
template<bool RELU>
__global__ __launch_bounds__(256) void pack_k(
    const float4* __restrict__ src, uint4* __restrict__ dst, int n4)
{
    const int base = blockIdx.x * 1024 + threadIdx.x;
    float4 v[4];
    #pragma unroll
    for (int j = 0; j < 4; j++) {
        const int i = base + j * 256;
        if (i < n4) v[j] = src[i];
    }
    #pragma unroll
    for (int j = 0; j < 4; j++) {
        const int i = base + j * 256;
        if (i < n4) {
            uint4 o;
            pack2<RELU>(make_float2(v[j].x, v[j].y), o.x, o.y);
            pack2<RELU>(make_float2(v[j].z, v[j].w), o.z, o.w);
            dst[i] = o;
        }
    }
}

// ---------------- packed bf16x3 mma.sync GEMM -------------------------------
// D[m][n] = sum_k a[m][k] * b[n][k], operands pre-split packed bf16 hi/lo.
//   LA/LB: 0 = row-major (M,K)/(N,K); 1 = transposed (K,M)/(K,N).
//   EP: 0 = fp32 out, 1 = fp32 tanh out, 2 = packed out, 3 = packed+relu out.
// Batch decode: h = bz & 7, q = bz >> 3; offsets = h*s? + q*s?2.
// M,N mult of 128; K mult of 32. 256 threads (8 warps, 2x4 warp grid).

#define STR     40
#define TILE_W  (128 * STR)
#define STAGE_B (TILE_W * 4)
#define SMEM_DYN (4 * STAGE_B)

template<int LA, int LB, int EP>
__global__ __launch_bounds__(256, 2) void gemm_p(
    const uint32_t* __restrict__ Ag, const uint32_t* __restrict__ Bg, void* Cg,
    int M, int N, int K, ll sA, ll sB, ll sC, ll sA2, ll sB2, ll sC2)
{
    extern __shared__ __align__(16) uint32_t smem[];
    const uint32_t sb = smem_u32(smem);

    const int bz = blockIdx.z;
    const int hz = bz & 7, qz = bz >> 3;
    const uint32_t* A = Ag + (ll)hz * sA + (ll)qz * sA2;
    const uint32_t* B = Bg + (ll)hz * sB + (ll)qz * sB2;
    const ll coff = (ll)hz * sC + (ll)qz * sC2;
    const int m0 = blockIdx.y * 128;
    const int n0 = blockIdx.x * 128;

    const int tid = threadIdx.x;
    const int wid = tid >> 5, lid = tid & 31;
    const int wm = wid >> 2, wn = wid & 3;
    const int g = lid >> 2, tg = lid & 3;

    float acc[4][4][4];
    #pragma unroll
    for (int mi = 0; mi < 4; mi++)
        #pragma unroll
        for (int ni = 0; ni < 4; ni++)
            #pragma unroll
            for (int r = 0; r < 4; r++) acc[mi][ni][r] = 0.f;

    auto issue = [&](int t) {
        const int st = t & 1;
        const uint32_t abase = sb + (uint32_t)(st * 2) * STAGE_B;
        const uint32_t bbase = abase + STAGE_B;
        const int k0 = t << 5;
        if (LA == 0) {
            #pragma unroll
            for (int i = 0; i < 4; i++) {
                int idx = tid + i * 256;
                int r = idx >> 3, kq = (idx & 7) << 2;
                cpa16(abase + (uint32_t)(r * STR + kq) * 4,
                      A + (ll)(m0 + r) * K + k0 + kq);
            }
        } else {
            #pragma unroll
            for (int i = 0; i < 16; i++) {
                int idx = tid + i * 256;
                int m = idx & 127, k = idx >> 7;
                cpa4(abase + (uint32_t)(m * STR + k) * 4,
                     A + (ll)(k0 + k) * M + m0 + m);
            }
        }
        if (LB == 0) {
            #pragma unroll
            for (int i = 0; i < 4; i++) {
                int idx = tid + i * 256;
                int r = idx >> 3, kq = (idx & 7) << 2;
                cpa16(bbase + (uint32_t)(r * STR + kq) * 4,
                      B + (ll)(n0 + r) * K + k0 + kq);
            }
        } else {
            #pragma unroll
            for (int i = 0; i < 16; i++) {
                int idx = tid + i * 256;
                int n = idx & 127, k = idx >> 7;
                cpa4(bbase + (uint32_t)(n * STR + k) * 4,
                     B + (ll)(k0 + k) * N + n0 + n);
            }
        }
    };

    const int T = K >> 5;
    issue(0);
    cp_commit();

    for (int t = 0; t < T; t++) {
        if (t + 1 < T) { issue(t + 1); cp_commit(); cp_wait<1>(); }
        else           { cp_wait<0>(); }
        __syncthreads();

        const uint32_t* As = smem + (t & 1) * 2 * TILE_W;
        const uint32_t* Bs = As + TILE_W;

        #pragma unroll
        for (int ks = 0; ks < 2; ks++) {
            const int kb = ks * 16;
            uint32_t bh[4][2], bl[4][2];
            #pragma unroll
            for (int ni = 0; ni < 4; ni++) {
                const uint32_t* p = Bs + (wn * 32 + ni * 8 + g) * STR + kb + 2 * tg;
                fragp(p,     bh[ni][0], bl[ni][0]);
                fragp(p + 8, bh[ni][1], bl[ni][1]);
            }
            #pragma unroll
            for (int mi = 0; mi < 4; mi++) {
                uint32_t ah[4], al[4];
                const uint32_t* p = As + (wm * 64 + mi * 16 + g) * STR + kb + 2 * tg;
                fragp(p,               ah[0], al[0]);
                fragp(p + 8 * STR,     ah[1], al[1]);
                fragp(p + 8,           ah[2], al[2]);
                fragp(p + 8 * STR + 8, ah[3], al[3]);
                #pragma unroll
                for (int ni = 0; ni < 4; ni++) {
                    mma16(acc[mi][ni], ah, bh[ni]);
                    mma16(acc[mi][ni], ah, bl[ni]);
                    mma16(acc[mi][ni], al, bh[ni]);
                }
            }
        }
        __syncthreads();
    }

    // ---- epilogue ----
    #pragma unroll
    for (int mi = 0; mi < 4; mi++) {
        #pragma unroll
        for (int ni = 0; ni < 4; ni++) {
            const int r0 = m0 + wm * 64 + mi * 16 + g;
            const int c  = n0 + wn * 32 + ni * 8 + 2 * tg;
            float2 v0 = make_float2(acc[mi][ni][0], acc[mi][ni][1]);
            float2 v1 = make_float2(acc[mi][ni][2], acc[mi][ni][3]);
            if (EP <= 1) {
                float* C = (float*)Cg + coff;
                if (EP == 1) {
                    v0.x = tanhf(v0.x); v0.y = tanhf(v0.y);
                    v1.x = tanhf(v1.x); v1.y = tanhf(v1.y);
                }
                *(float2*)(C + (ll)r0 * N + c)       = v0;
                *(float2*)(C + (ll)(r0 + 8) * N + c) = v1;
            } else {
                uint32_t* C = (uint32_t*)Cg + coff;
                uint2 w0, w1;
                pack2<EP == 3>(v0, w0.x, w0.y);
                pack2<EP == 3>(v1, w1.x, w1.y);
                *(uint2*)(C + (ll)r0 * N + c)       = w0;
                *(uint2*)(C + (ll)(r0 + 8) * N + c) = w1;
            }
        }
    }
}

// ---------------- fused residual-add + LayerNorm -> packed output -----------
template<bool RELU>
__global__ __launch_bounds__(256) void add_ln_k(
    const float* __restrict__ x, const float* __restrict__ m,
    const float* __restrict__ g, const float* __restrict__ b,
    uint32_t* __restrict__ o)
{
    const int row = blockIdx.x;
    const ll off = (ll)row * SS;
    float2 v[2];
    float sum = 0.f, sq = 0.f;
    #pragma unroll
    for (int j = 0; j < 2; j++) {
        int i2 = threadIdx.x * 2 + j * 512;
        float2 xv = *(const float2*)(x + off + i2);
        float2 mv = *(const float2*)(m + off + i2);
        v[j] = make_float2(xv.x + mv.x, xv.y + mv.y);
        sum += v[j].x + v[j].y;
        sq  += v[j].x * v[j].x + v[j].y * v[j].y;
    }
    #pragma unroll
    for (int o2 = 16; o2; o2 >>= 1) {
        sum += __shfl_xor_sync(0xffffffffu, sum, o2);
        sq  += __shfl_xor_sync(0xffffffffu, sq,  o2);
    }
    __shared__ float rs[8], rq[8];
    const int w = threadIdx.x >> 5, l = threadIdx.x & 31;
    if (l == 0) { rs[w] = sum; rq[w] = sq; }
    __syncthreads();
    if (w == 0) {
        float s2 = (l < 8) ? rs[l] : 0.f;
        float q2 = (l < 8) ? rq[l] : 0.f;
        #pragma unroll
        for (int o2 = 4; o2; o2 >>= 1) {
            s2 += __shfl_xor_sync(0xffffffffu, s2, o2);
            q2 += __shfl_xor_sync(0xffffffffu, q2, o2);
        }
        if (l == 0) { rs[0] = s2; rq[0] = q2; }
    }
    __syncthreads();
    const float mu  = rs[0] * (1.f / SS);
    const float var = rq[0] * (1.f / SS) - mu * mu;
    const float inv = rsqrtf(var + 1e-6f);
    #pragma unroll
    for (int j = 0; j < 2; j++) {
        int i2 = threadIdx.x * 2 + j * 512;
        float2 gv = *(const float2*)(g + i2);
        float2 bv = *(const float2*)(b + i2);
        float2 t = make_float2((v[j].x - mu) * inv * gv.x + bv.x,
                               (v[j].y - mu) * inv * gv.y + bv.y);
        uint2 wo;
        pack2<RELU>(t, wo.x, wo.y);
        *(uint2*)(o + off + i2) = wo;
    }
}

// ---------------- host orchestration ----------------------------------------
extern "C" void kernel_launch(void* const* d_in, const int* in_sizes, int n_in,
                              void* d_out, int out_size)
{
    const float* inp    = (const float*)d_in[0];
    const float* enc_k  = (const float*)d_in[1];
    const float* enc_v  = (const float*)d_in[2];
    const float* w_qkv1 = (const float*)d_in[3];
    const float* w_qkv2 = (const float*)d_in[4];
    const float* mh1_W1 = (const float*)d_in[5];
    const float* mh1_W2 = (const float*)d_in[6];
    const float* mh2_W1 = (const float*)d_in[7];
    const float* mh2_W2 = (const float*)d_in[8];
    const float* c1_w1  = (const float*)d_in[9];
    const float* c1_w2  = (const float*)d_in[10];
    const float* c2_w1  = (const float*)d_in[11];
    const float* c2_w2  = (const float*)d_in[12];
    const float* l1_w1  = (const float*)d_in[13];
    const float* l1_w2  = (const float*)d_in[14];
    const float* l2_w1  = (const float*)d_in[15];
    const float* l2_w2  = (const float*)d_in[16];
    const float* gamma  = (const float*)d_in[17];
    const float* beta   = (const float*)d_in[18];
    float* out = (float*)d_out;

    uint32_t *qkv, *qkv2, *z, *s, *bm, *att, *y, *hb, *x1, *x2;
    uint32_t *pinp, *pw1, *pw2;
    uint32_t *W1a, *W2a, *W1b, *W2b, *c1a, *c2a, *c1b, *c2b;
    uint32_t *lw11, *lw12, *lw21, *lw22;
    float* mb;
    cudaGetSymbolAddress((void**)&qkv,  p_qkv);
    cudaGetSymbolAddress((void**)&qkv2, p_qkv2);
    cudaGetSymbolAddress((void**)&z,    p_z);
    cudaGetSymbolAddress((void**)&s,    p_s);
    cudaGetSymbolAddress((void**)&bm,   p_bm);
    cudaGetSymbolAddress((void**)&att,  p_att);
    cudaGetSymbolAddress((void**)&y,    p_y);
    cudaGetSymbolAddress((void**)&hb,   p_h);
    cudaGetSymbolAddress((void**)&x1,   p_x1);
    cudaGetSymbolAddress((void**)&x2,   p_x2);
    cudaGetSymbolAddress((void**)&mb,   g_m);
    cudaGetSymbolAddress((void**)&pinp, p_inp);
    cudaGetSymbolAddress((void**)&pw1,  p_wqkv1);
    cudaGetSymbolAddress((void**)&pw2,  p_wqkv2);
    cudaGetSymbolAddress((void**)&W1a,  p_W1a);
    cudaGetSymbolAddress((void**)&W2a,  p_W2a);
    cudaGetSymbolAddress((void**)&W1b,  p_W1b);
    cudaGetSymbolAddress((void**)&W2b,  p_W2b);
    cudaGetSymbolAddress((void**)&c1a,  p_c1w1);
    cudaGetSymbolAddress((void**)&c2a,  p_c2w1);
    cudaGetSymbolAddress((void**)&c1b,  p_c1w2);
    cudaGetSymbolAddress((void**)&c2b,  p_c2w2);
    cudaGetSymbolAddress((void**)&lw11, p_l1w1);
    cudaGetSymbolAddress((void**)&lw12, p_l1w2);
    cudaGetSymbolAddress((void**)&lw21, p_l2w1);
    cudaGetSymbolAddress((void**)&lw22, p_l2w2);

    cudaFuncSetAttribute(gemm_p<0,0,0>, cudaFuncAttributeMaxDynamicSharedMemorySize, SMEM_DYN);
    cudaFuncSetAttribute(gemm_p<0,0,1>, cudaFuncAttributeMaxDynamicSharedMemorySize, SMEM_DYN);
    cudaFuncSetAttribute(gemm_p<0,0,2>, cudaFuncAttributeMaxDynamicSharedMemorySize, SMEM_DYN);
    cudaFuncSetAttribute(gemm_p<0,0,3>, cudaFuncAttributeMaxDynamicSharedMemorySize, SMEM_DYN);
    cudaFuncSetAttribute(gemm_p<0,1,3>, cudaFuncAttributeMaxDynamicSharedMemorySize, SMEM_DYN);
    cudaFuncSetAttribute(gemm_p<1,1,2>, cudaFuncAttributeMaxDynamicSharedMemorySize, SMEM_DYN);
    cudaFuncSetAttribute(gemm_p<1,0,3>, cudaFuncAttributeMaxDynamicSharedMemorySize, SMEM_DYN);

    auto pk = [&](const float* src, uint32_t* dst, ll n, bool relu) {
        const int n4 = (int)(n >> 2);
        const int gr = (n4 + 1023) / 1024;
        if (relu) pack_k<true ><<<gr, 256>>>((const float4*)src, (uint4*)dst, n4);
        else      pack_k<false><<<gr, 256>>>((const float4*)src, (uint4*)dst, n4);
    };

    const ll DS  = (ll)DD * SS;
    const ll DM  = (ll)DD * MIDD;
    const ll MS  = (ll)MIDD * SS;
    const ll SM  = (ll)SS * MIDD;
    const ll WSZ = (ll)HH * 3 * MIDD * SS;

    // ---- one-time packing of inputs & weights ----
    pk(inp,    pinp,  DS, false);
    pk(enc_k,  qkv2 + DS,      DS, true);   // block2 slot 1 (consumed via relu)
    pk(enc_v,  qkv2 + 2ll * DS, DS, true);  // block2 slot 2
    pk(w_qkv1, pw1,   3ll * DD * DD, false);
    pk(w_qkv2, pw2,   (ll)DD * DD,   false);
    pk(mh1_W1, W1a,   WSZ, false);
    pk(mh1_W2, W2a,   WSZ, false);
    pk(mh2_W1, W1b,   WSZ, false);
    pk(mh2_W2, W2b,   WSZ, false);
    pk(c1_w1,  c1a,   (ll)MIDD * HH * DD, false);
    pk(c2_w1,  c2a,   (ll)MIDD * HH * DD, false);
    pk(c1_w2,  c1b,   (ll)DD * MIDD, false);
    pk(c2_w2,  c2b,   (ll)DD * MIDD, false);
    pk(l1_w1,  lw11,  (ll)MIDD * SS,   false);
    pk(l1_w2,  lw12,  (ll)SOUT * MIDD, false);
    pk(l2_w1,  lw21,  (ll)MIDD * SOUT, false);
    pk(l2_w2,  lw22,  (ll)SOUT * MIDD, false);

    auto run_block = [&](const uint32_t* qarr,
                         const uint32_t* W1, const uint32_t* W2,
                         const uint32_t* cw1, const uint32_t* cw2) {
        // merged z: grid.z = 24 (q = bz>>3, h = bz&7)
        // z[q,h] = relu-packed( qarr[q] @ W1[h,q]^T )   (D, MID)
        gemm_p<0,0,3><<<dim3(MIDD / 128, DD / 128, 24), 256, SMEM_DYN>>>(
            qarr, W1, z,
            DD, MIDD, SS,
            /*sA*/0,        /*sB*/3ll * MS, /*sC*/DM,
            /*sA2*/DS,      /*sB2*/MS,      /*sC2*/(ll)HH * DM);
        // merged s: s[h,q] = z[q,h] @ W2[h,q]^T   (D, S), layout (h, q, d, s)
        gemm_p<0,0,2><<<dim3(SS / 128, DD / 128, 24), 256, SMEM_DYN>>>(
            z, W2, s,
            DD, SS, MIDD,
            /*sA*/DM,       /*sB*/3ll * SM, /*sC*/3ll * DS,
            /*sA2*/(ll)HH * DM, /*sB2*/SM,  /*sC2*/DS);
        // b[h] = k^T q : A = sk (K=D, M=S) LA=1; B = sq (K=D, N=S) LB=1
        gemm_p<1,1,2><<<dim3(SS / 128, SS / 128, HH), 256, SMEM_DYN>>>(
            s + DS, s, bm, SS, SS, DD, 3ll * DS, 3ll * DS, (ll)SS * SS, 0, 0, 0);
        // att[h] = v @ b : A = sv (D, S) LA=0; B = b (K=s, N=t) LB=1 -> packed+relu
        gemm_p<0,1,3><<<dim3(SS / 128, DD / 128, HH), 256, SMEM_DYN>>>(
            s + 2ll * DS, bm, att, DD, SS, SS, 3ll * DS, (ll)SS * SS, DS, 0, 0, 0);
        // y = relu(cat)^T @ cw1^T : A = att (K=H*D, M=S) LA=1; B = cw1 (N,K) LB=0
        gemm_p<1,0,3><<<dim3(MIDD / 128, SS / 128, 1), 256, SMEM_DYN>>>(
            att, cw1, y, SS, MIDD, HH * DD, 0, 0, 0, 0, 0, 0);
        // m = cw2 @ relu(y)^T : fp32
        gemm_p<0,0,0><<<dim3(SS / 128, DD / 128, 1), 256, SMEM_DYN>>>(
            cw2, y, mb, DD, SS, MIDD, 0, 0, 0, 0, 0, 0);
    };

    // qkv1[q] = w_qkv1[q] @ inp  (grid.z = 3 -> h = 0..2 rides per-q stride)
    gemm_p<0,1,3><<<dim3(SS / 128, DD / 128, 3), 256, SMEM_DYN>>>(
        pw1, pinp, qkv, DD, SS, DD, (ll)DD * DD, 0, DS, 0, 0, 0);

    run_block(qkv, W1a, W2a, c1a, c1b);
    add_ln_k<false><<<DD, 256>>>(inp, mb, gamma, beta, hb);   // h1 packed plain

    // q2 = w_qkv2[0] @ h1 -> qkv2 slot 0 (packed+relu)
    gemm_p<0,1,3><<<dim3(SS / 128, DD / 128, 1), 256, SMEM_DYN>>>(
        pw2, hb, qkv2, DD, SS, DD, 0, 0, 0, 0, 0, 0);

    run_block(qkv2, W1b, W2b, c2a, c2b);
    add_ln_k<true><<<DD, 256>>>(inp, mb, gamma, beta, hb);    // h2 packed+relu

    // x1 = relu(h2) @ l1_w1^T
    gemm_p<0,0,3><<<dim3(MIDD / 128, DD / 128, 1), 256, SMEM_DYN>>>(
        hb, lw11, x1, DD, MIDD, SS, 0, 0, 0, 0, 0, 0);
    // x2 = relu(x1) @ l1_w2^T
    gemm_p<0,0,3><<<dim3(SOUT / 128, DD / 128, 1), 256, SMEM_DYN>>>(
        x1, lw12, x2, DD, SOUT, MIDD, 0, 0, 0, 0, 0, 0);
    // y1 = relu(x2) @ l2_w1^T
    gemm_p<0,0,3><<<dim3(MIDD / 128, DD / 128, 1), 256, SMEM_DYN>>>(
        x2, lw21, x1, DD, MIDD, SOUT, 0, 0, 0, 0, 0, 0);
    // out = tanh(relu(y1) @ l2_w2^T)
    gemm_p<0,0,1><<<dim3(SOUT / 128, DD / 128, 1), 256, SMEM_DYN>>>(
        x1, lw22, out, DD, SOUT, MIDD, 0, 0, 0, 0, 0, 0);
}